// round 5
// baseline (speedup 1.0000x reference)
#include <cuda_runtime.h>

#define WARPS 4
#define PTS 2
#define FULLMASK 0xffffffffu

__device__ __forceinline__ unsigned long long pk2(float x, float y) {
    unsigned long long r;
    asm("mov.b64 %0,{%1,%2};" : "=l"(r) : "f"(x), "f"(y));
    return r;
}
__device__ __forceinline__ void upk2(unsigned long long v, float& x, float& y) {
    asm("mov.b64 {%0,%1},%2;" : "=f"(x), "=f"(y) : "l"(v));
}
__device__ __forceinline__ void ffma2(unsigned long long& d, unsigned long long a,
                                      unsigned long long b) {
    asm("fma.rn.f32x2 %0,%1,%2,%0;" : "+l"(d) : "l"(a), "l"(b));
}

__global__ void __launch_bounds__(128, 7) arek(
    const float* __restrict__ q_pts, const float* __restrict__ s_pts,
    const int*   __restrict__ nbr,
    const float* __restrict__ wb,     const float* __restrict__ w_vn,
    const float* __restrict__ wd_vn,  const float* __restrict__ w_h1,
    const float* __restrict__ w_h2,   const float* __restrict__ b_h2,
    const float* __restrict__ wd_relu,const float* __restrict__ w_un,
    const float* __restrict__ wd_un,
    float* __restrict__ out, int N)
{
    // ---- small weights only (big tables stay in L1 via __ldg) ----
    __shared__ float4 s_wvnu[16][2];                 // [o] -> {w0,w1,w2,_},{u0,u1,u2,_}
    __shared__ __align__(16) float s_wh1[128];       // [16][8] row-major
    __shared__ __align__(16) float s_wh2[64];        // [8][8]  row-major
    __shared__ __align__(16) float s_bh2[8];
    __shared__ float s_wb[768];
    // ---- per-warp scratch ----
    __shared__ float4 s_localv[WARPS][PTS][16][3];
    __shared__ float4 s_scorev[WARPS][PTS][16][2];
    __shared__ float4 s_featv [WARPS][PTS][32];

    const int tid = threadIdx.x;
    if (tid < 16) {
        const int o = tid;
        s_wvnu[o][0] = make_float4(w_vn [o], w_vn [16+o], w_vn [32+o], 0.0f);
        s_wvnu[o][1] = make_float4(wd_vn[o], wd_vn[16+o], wd_vn[32+o], 0.0f);
    }
    s_wh1[tid] = w_h1[tid];
    if (tid < 64) s_wh2[tid] = w_h2[tid];
    if (tid < 8)  s_bh2[tid] = b_h2[tid];
    #pragma unroll
    for (int i = tid; i < 768; i += 128) s_wb[i] = wb[i];
    __syncthreads();

    const int warp = tid >> 5, lane = tid & 31;
    const int n0 = blockIdx.x * (WARPS * PTS) + warp * PTS;
    if (n0 >= N) return;

    const float BN = 0.99999500003749968f;   // 1/sqrt(1+1e-5)

    // ================= Phase 1: lane = (p, k) — one neighbor per lane =================
    {
        const int pp = lane >> 4;            // point within pair
        const int k  = lane & 15;            // neighbor
        const int n  = (n0 + pp < N) ? (n0 + pp) : (N - 1);

        const float qx = q_pts[n*3+0], qy = q_pts[n*3+1], qz = q_pts[n*3+2];
        const int idx = nbr[n*16 + k];
        const float px = s_pts[idx*3+0] - qx;
        const float py = s_pts[idx*3+1] - qy;
        const float pz = s_pts[idx*3+2] - qz;

        float sx = px, sy = py, sz = pz;
        #pragma unroll
        for (int off = 1; off < 16; off <<= 1) {
            sx += __shfl_xor_sync(FULLMASK, sx, off);
            sy += __shfl_xor_sync(FULLMASK, sy, off);
            sz += __shfl_xor_sync(FULLMASK, sz, off);
        }
        const float cx = sx * (1.0f/16.0f);
        const float cy = sy * (1.0f/16.0f);
        const float cz = sz * (1.0f/16.0f);

        const float rx = py*cz - pz*cy;
        const float ry = pz*cx - px*cz;
        const float rz = px*cy - py*cx;

        s_localv[warp][pp][k][0] = make_float4(px, py, pz, 0.0f);
        s_localv[warp][pp][k][1] = make_float4(cx, cy, cz, 0.0f);
        s_localv[warp][pp][k][2] = make_float4(rx, ry, rz, 0.0f);

        // VN 3->16 + VN-leakyReLU + norm, fused into the h1 matvec
        const float4* wh1v = (const float4*)s_wh1;
        float acc[8] = {0,0,0,0,0,0,0,0};
        #pragma unroll
        for (int c = 0; c < 16; c++) {
            const float4 W = s_wvnu[c][0];
            const float4 U = s_wvnu[c][1];
            const float p0 = BN*(px*W.x + cx*W.y + rx*W.z);
            const float p1 = BN*(py*W.x + cy*W.y + ry*W.z);
            const float p2 = BN*(pz*W.x + cz*W.y + rz*W.z);
            const float d0 = px*U.x + cx*U.y + rx*U.z;
            const float d1 = py*U.x + cy*U.y + ry*U.z;
            const float d2 = pz*U.x + cz*U.y + rz*U.z;
            const float dot = p0*d0 + p1*d1 + p2*d2;
            const float dsq = d0*d0 + d1*d1 + d2*d2;
            const float f = (dot >= 0.0f) ? 0.0f : (0.8f * __fdividef(dot, dsq + 1e-6f));
            const float s0 = p0 - f*d0, s1 = p1 - f*d1, s2 = p2 - f*d2;
            const float sn = sqrtf(s0*s0 + s1*s1 + s2*s2);
            const float4 r0 = wh1v[c*2 + 0];
            const float4 r1 = wh1v[c*2 + 1];
            acc[0] += sn*r0.x; acc[1] += sn*r0.y; acc[2] += sn*r0.z; acc[3] += sn*r0.w;
            acc[4] += sn*r1.x; acc[5] += sn*r1.y; acc[6] += sn*r1.z; acc[7] += sn*r1.w;
        }
        #pragma unroll
        for (int o = 0; o < 8; o++) acc[o] = fmaxf(0.0f, BN * acc[o]);

        // h2 + softmax over 8 channels
        const float4* wh2v = (const float4*)s_wh2;
        const float4 bA = ((const float4*)s_bh2)[0];
        const float4 bB = ((const float4*)s_bh2)[1];
        float h2[8] = {bA.x, bA.y, bA.z, bA.w, bB.x, bB.y, bB.z, bB.w};
        #pragma unroll
        for (int c = 0; c < 8; c++) {
            const float4 r0 = wh2v[c*2 + 0];
            const float4 r1 = wh2v[c*2 + 1];
            const float s = acc[c];
            h2[0] += s*r0.x; h2[1] += s*r0.y; h2[2] += s*r0.z; h2[3] += s*r0.w;
            h2[4] += s*r1.x; h2[5] += s*r1.y; h2[6] += s*r1.z; h2[7] += s*r1.w;
        }
        float m = h2[0];
        #pragma unroll
        for (int o = 1; o < 8; o++) m = fmaxf(m, h2[o]);
        float se = 0.0f;
        #pragma unroll
        for (int o = 0; o < 8; o++) { h2[o] = __expf(h2[o] - m); se += h2[o]; }
        const float ise = __fdividef(1.0f, se);
        s_scorev[warp][pp][k][0] = make_float4(h2[0]*ise, h2[1]*ise, h2[2]*ise, h2[3]*ise);
        s_scorev[warp][pp][k][1] = make_float4(h2[4]*ise, h2[5]*ise, h2[6]*ise, h2[7]*ise);
    }
    __syncwarp();

    // ======= Phase 2: kernel-point correlation, lane = output channel h =======
    float wb0[8], wb1[8], wb2[8];
    #pragma unroll
    for (int ks = 0; ks < 8; ks++) {
        wb0[ks] = s_wb[      ks*32 + lane];
        wb1[ks] = s_wb[256 + ks*32 + lane];
        wb2[ks] = s_wb[512 + ks*32 + lane];
    }
    #pragma unroll
    for (int p = 0; p < PTS; p++) {
        float f0 = 0.0f, f1 = 0.0f, f2 = 0.0f;
        #pragma unroll
        for (int kk = 0; kk < 16; kk++) {
            const float4 sA = s_scorev[warp][p][kk][0];
            const float4 sB = s_scorev[warp][p][kk][1];
            const float we0 = sA.x*wb0[0] + sA.y*wb0[1] + sA.z*wb0[2] + sA.w*wb0[3]
                            + sB.x*wb0[4] + sB.y*wb0[5] + sB.z*wb0[6] + sB.w*wb0[7];
            const float we1 = sA.x*wb1[0] + sA.y*wb1[1] + sA.z*wb1[2] + sA.w*wb1[3]
                            + sB.x*wb1[4] + sB.y*wb1[5] + sB.z*wb1[6] + sB.w*wb1[7];
            const float we2 = sA.x*wb2[0] + sA.y*wb2[1] + sA.z*wb2[2] + sA.w*wb2[3]
                            + sB.x*wb2[4] + sB.y*wb2[5] + sB.z*wb2[6] + sB.w*wb2[7];
            const float4 P = s_localv[warp][p][kk][0];
            const float4 C = s_localv[warp][p][kk][1];
            const float4 R = s_localv[warp][p][kk][2];
            const float p0 = P.x*we0 + C.x*we1 + R.x*we2;
            const float p1 = P.y*we0 + C.y*we1 + R.y*we2;
            const float p2 = P.z*we0 + C.z*we1 + R.z*we2;
            const float nn = p0*p0 + p1*p1 + p2*p2;
            const float iv = rsqrtf(fmaxf(nn, 1e-24f));
            f0 += p0*iv; f1 += p1*iv; f2 += p2*iv;
        }
        s_featv[warp][p][lane] = make_float4(f0*(1.0f/16.0f), f1*(1.0f/16.0f), f2*(1.0f/16.0f), 0.0f);
    }
    __syncwarp();

    // ======= Phase 3a: VNLeakyReLU(32->32), weights via L1 (__ldg) =======
    {
        float f[PTS][3], g[PTS][3];
        #pragma unroll
        for (int p = 0; p < PTS; p++) {
            const float4 F = s_featv[warp][p][lane];
            f[p][0] = F.x; f[p][1] = F.y; f[p][2] = F.z;
            g[p][0] = 0.0f; g[p][1] = 0.0f; g[p][2] = 0.0f;
        }
        #pragma unroll
        for (int h = 0; h < 32; h++) {
            const float w = __ldg(wd_relu + h*32 + lane);
            #pragma unroll
            for (int p = 0; p < PTS; p++) {
                const float4 F = s_featv[warp][p][h];
                g[p][0] += F.x * w; g[p][1] += F.y * w; g[p][2] += F.z * w;
            }
        }
        __syncwarp();
        #pragma unroll
        for (int p = 0; p < PTS; p++) {
            const float dot = f[p][0]*g[p][0] + f[p][1]*g[p][1] + f[p][2]*g[p][2];
            const float dsq = g[p][0]*g[p][0] + g[p][1]*g[p][1] + g[p][2]*g[p][2];
            const float fc = (dot >= 0.0f) ? 0.0f : (0.8f * __fdividef(dot, dsq + 1e-6f));
            s_featv[warp][p][lane] = make_float4(f[p][0] - fc*g[p][0],
                                                 f[p][1] - fc*g[p][1],
                                                 f[p][2] - fc*g[p][2], 0.0f);
        }
    }
    __syncwarp();

    // ======= Phase 3b: VNLinearLeakyReLU(32->64), weights via L1, f32x2-packed =======
    {
        unsigned long long a01[PTS], b01[PTS], A01[PTS], B01[PTS];
        float a2[PTS], b2[PTS], A2[PTS], B2[PTS];
        #pragma unroll
        for (int p = 0; p < PTS; p++) {
            a01[p] = 0ull; b01[p] = 0ull; A01[p] = 0ull; B01[p] = 0ull;
            a2[p] = 0.0f;  b2[p] = 0.0f;  A2[p] = 0.0f;  B2[p] = 0.0f;
        }
        #pragma unroll
        for (int h = 0; h < 32; h++) {
            const float wa0 = __ldg(w_un  + h*64 + lane);
            const float wa1 = __ldg(w_un  + h*64 + lane + 32);
            const float wd0 = __ldg(wd_un + h*64 + lane);
            const float wd1 = __ldg(wd_un + h*64 + lane + 32);
            const unsigned long long w0x = pk2(wa0, wa0);
            const unsigned long long w0y = pk2(wd0, wd0);
            const unsigned long long w1x = pk2(wa1, wa1);
            const unsigned long long w1y = pk2(wd1, wd1);
            #pragma unroll
            for (int p = 0; p < PTS; p++) {
                const float4 F = s_featv[warp][p][h];
                const unsigned long long fxy = pk2(F.x, F.y);
                ffma2(a01[p], fxy, w0x); a2[p] += F.z * wa0;
                ffma2(b01[p], fxy, w0y); b2[p] += F.z * wd0;
                ffma2(A01[p], fxy, w1x); A2[p] += F.z * wa1;
                ffma2(B01[p], fxy, w1y); B2[p] += F.z * wd1;
            }
        }
        #pragma unroll
        for (int p = 0; p < PTS; p++) {
            if (n0 + p >= N) break;
            const int n = n0 + p;
            float a0, a1, b0, b1, A0, A1, B0, B1;
            upk2(a01[p], a0, a1); upk2(b01[p], b0, b1);
            upk2(A01[p], A0, A1); upk2(B01[p], B0, B1);
            {
                const int j = lane;
                const float x0 = BN*a0, x1 = BN*a1, x2 = BN*a2[p];
                const float dt = x0*b0 + x1*b1 + x2*b2[p];
                const float dq = b0*b0 + b1*b1 + b2[p]*b2[p];
                const float fc = (dt >= 0.0f) ? 0.0f : (0.8f * __fdividef(dt, dq + 1e-6f));
                out[n*192 + j*3 + 0] = x0 - fc*b0;
                out[n*192 + j*3 + 1] = x1 - fc*b1;
                out[n*192 + j*3 + 2] = x2 - fc*b2[p];
            }
            {
                const int j = lane + 32;
                const float x0 = BN*A0, x1 = BN*A1, x2 = BN*A2[p];
                const float dt = x0*B0 + x1*B1 + x2*B2[p];
                const float dq = B0*B0 + B1*B1 + B2[p]*B2[p];
                const float fc = (dt >= 0.0f) ? 0.0f : (0.8f * __fdividef(dt, dq + 1e-6f));
                out[n*192 + j*3 + 0] = x0 - fc*B0;
                out[n*192 + j*3 + 1] = x1 - fc*B1;
                out[n*192 + j*3 + 2] = x2 - fc*B2[p];
            }
        }
    }
}

extern "C" void kernel_launch(void* const* d_in, const int* in_sizes, int n_in,
                              void* d_out, int out_size) {
    const float* q_pts   = (const float*)d_in[0];
    const float* s_pts   = (const float*)d_in[1];
    const int*   nbr     = (const int*)  d_in[3];
    const float* wb      = (const float*)d_in[4];
    const float* w_vn    = (const float*)d_in[5];
    const float* wd_vn   = (const float*)d_in[6];
    const float* w_h1    = (const float*)d_in[7];
    const float* w_h2    = (const float*)d_in[8];
    const float* b_h2    = (const float*)d_in[9];
    const float* wd_relu = (const float*)d_in[10];
    const float* w_un    = (const float*)d_in[11];
    const float* wd_un   = (const float*)d_in[12];

    const int N = in_sizes[0] / 3;
    const int per_block = WARPS * PTS;
    const int blocks = (N + per_block - 1) / per_block;
    arek<<<blocks, 128>>>(q_pts, s_pts, nbr, wb, w_vn, wd_vn, w_h1, w_h2, b_h2,
                          wd_relu, w_un, wd_un, (float*)d_out, N);
}

// round 6
// speedup vs baseline: 1.1420x; 1.1420x over previous
#include <cuda_runtime.h>

typedef unsigned long long u64;
#define WARPS 4
#define PTS 2
#define FULLMASK 0xffffffffu

__device__ __forceinline__ u64 pk2(float x, float y) {
    u64 r; asm("mov.b64 %0,{%1,%2};" : "=l"(r) : "f"(x), "f"(y)); return r;
}
__device__ __forceinline__ void upk2(u64 v, float& x, float& y) {
    asm("mov.b64 {%0,%1},%2;" : "=f"(x), "=f"(y) : "l"(v));
}
__device__ __forceinline__ u64 fma2(u64 a, u64 b, u64 c) {
    u64 d; asm("fma.rn.f32x2 %0,%1,%2,%3;" : "=l"(d) : "l"(a), "l"(b), "l"(c)); return d;
}
__device__ __forceinline__ u64 mul2(u64 a, u64 b) {
    u64 d; asm("mul.rn.f32x2 %0,%1,%2;" : "=l"(d) : "l"(a), "l"(b)); return d;
}

__global__ void __launch_bounds__(128, 5) arek(
    const float* __restrict__ q_pts, const float* __restrict__ s_pts,
    const int*   __restrict__ nbr,
    const float* __restrict__ wb,     const float* __restrict__ w_vn,
    const float* __restrict__ wd_vn,  const float* __restrict__ w_h1,
    const float* __restrict__ w_h2,   const float* __restrict__ b_h2,
    const float* __restrict__ wd_relu,const float* __restrict__ w_un,
    const float* __restrict__ wd_un,
    float* __restrict__ out, int N)
{
    const float BN = 0.99999500003749968f;   // 1/sqrt(1+1e-5)

    // ---- pre-packed weights (channel pairs) ----
    __shared__ u64 s_wvnu2[8][6];   // [pc] -> {wx,wy,wz,ux,uy,uz} pairs (BN folded into w)
    __shared__ u64 s_wh1p[8][8];    // [pc][o] -> (BN*w_h1[2pc][o], BN*w_h1[2pc+1][o])
    __shared__ __align__(16) float s_wh2[64];   // [8][8] row-major
    __shared__ __align__(16) float s_bh2[8];
    __shared__ float s_wb[768];
    // ---- per-warp scratch, packed over the 2 points ----
    __shared__ u64 s_local2[WARPS][16][9];  // [k][comp] -> (p0,p1); comps: p,c,r xyz
    __shared__ u64 s_score2[WARPS][16][9];  // [k][ks]   -> (p0,p1); 9 = pad (conflict-free)
    __shared__ u64 s_feat2 [WARPS][32][3];  // [h][comp] -> (p0,p1)

    const int tid = threadIdx.x;
    if (tid < 8) {
        const int pc = tid, c0 = 2*pc, c1 = 2*pc + 1;
        s_wvnu2[pc][0] = pk2(BN*w_vn[c0],      BN*w_vn[c1]);
        s_wvnu2[pc][1] = pk2(BN*w_vn[16+c0],   BN*w_vn[16+c1]);
        s_wvnu2[pc][2] = pk2(BN*w_vn[32+c0],   BN*w_vn[32+c1]);
        s_wvnu2[pc][3] = pk2(wd_vn[c0],        wd_vn[c1]);
        s_wvnu2[pc][4] = pk2(wd_vn[16+c0],     wd_vn[16+c1]);
        s_wvnu2[pc][5] = pk2(wd_vn[32+c0],     wd_vn[32+c1]);
    }
    if (tid < 64) {
        const int pc = tid >> 3, o = tid & 7;
        s_wh1p[pc][o] = pk2(BN*w_h1[(2*pc)*8 + o], BN*w_h1[(2*pc+1)*8 + o]);
        s_wh2[tid] = w_h2[tid];
    }
    if (tid < 8)  s_bh2[tid] = b_h2[tid];
    #pragma unroll
    for (int i = tid; i < 768; i += 128) s_wb[i] = wb[i];
    __syncthreads();

    const int warp = tid >> 5, lane = tid & 31;
    const int n0 = blockIdx.x * (WARPS * PTS) + warp * PTS;
    if (n0 >= N) return;

    // ================= Phase 1: lane = (p, k), channel-pair packed =================
    {
        const int pp = lane >> 4;            // point within pair
        const int k  = lane & 15;            // neighbor
        const int n  = (n0 + pp < N) ? (n0 + pp) : (N - 1);

        const float qx = q_pts[n*3+0], qy = q_pts[n*3+1], qz = q_pts[n*3+2];
        const int idx = nbr[n*16 + k];
        const float px = s_pts[idx*3+0] - qx;
        const float py = s_pts[idx*3+1] - qy;
        const float pz = s_pts[idx*3+2] - qz;

        float sx = px, sy = py, sz = pz;
        #pragma unroll
        for (int off = 1; off < 16; off <<= 1) {
            sx += __shfl_xor_sync(FULLMASK, sx, off);
            sy += __shfl_xor_sync(FULLMASK, sy, off);
            sz += __shfl_xor_sync(FULLMASK, sz, off);
        }
        const float cx = sx * (1.0f/16.0f);
        const float cy = sy * (1.0f/16.0f);
        const float cz = sz * (1.0f/16.0f);

        const float rx = py*cz - pz*cy;
        const float ry = pz*cx - px*cz;
        const float rz = px*cy - py*cx;

        // write geometry into the point-packed table (scalar halves)
        ((float*)&s_local2[warp][k][0])[pp] = px;
        ((float*)&s_local2[warp][k][1])[pp] = py;
        ((float*)&s_local2[warp][k][2])[pp] = pz;
        ((float*)&s_local2[warp][k][3])[pp] = cx;
        ((float*)&s_local2[warp][k][4])[pp] = cy;
        ((float*)&s_local2[warp][k][5])[pp] = cz;
        ((float*)&s_local2[warp][k][6])[pp] = rx;
        ((float*)&s_local2[warp][k][7])[pp] = ry;
        ((float*)&s_local2[warp][k][8])[pp] = rz;

        // duplicated-geometry packs (hoisted)
        const u64 PX = pk2(px,px), PY = pk2(py,py), PZ = pk2(pz,pz);
        const u64 CX = pk2(cx,cx), CY = pk2(cy,cy), CZ = pk2(cz,cz);
        const u64 RX = pk2(rx,rx), RY = pk2(ry,ry), RZ = pk2(rz,rz);

        u64 acc2[8] = {0,0,0,0,0,0,0,0};
        #pragma unroll
        for (int pc = 0; pc < 8; pc++) {
            const u64 wx = s_wvnu2[pc][0], wy = s_wvnu2[pc][1], wz = s_wvnu2[pc][2];
            const u64 ux = s_wvnu2[pc][3], uy = s_wvnu2[pc][4], uz = s_wvnu2[pc][5];
            const u64 p0 = fma2(PX, wx, fma2(CX, wy, mul2(RX, wz)));
            const u64 p1 = fma2(PY, wx, fma2(CY, wy, mul2(RY, wz)));
            const u64 p2 = fma2(PZ, wx, fma2(CZ, wy, mul2(RZ, wz)));
            const u64 d0 = fma2(PX, ux, fma2(CX, uy, mul2(RX, uz)));
            const u64 d1 = fma2(PY, ux, fma2(CY, uy, mul2(RY, uz)));
            const u64 d2 = fma2(PZ, ux, fma2(CZ, uy, mul2(RZ, uz)));
            const u64 dot2 = fma2(p0, d0, fma2(p1, d1, mul2(p2, d2)));
            const u64 dsq2 = fma2(d0, d0, fma2(d1, d1, mul2(d2, d2)));
            float dta, dtb, dqa, dqb;
            upk2(dot2, dta, dtb); upk2(dsq2, dqa, dqb);
            const float nfa = (dta >= 0.0f) ? 0.0f : (-0.8f * __fdividef(dta, dqa + 1e-6f));
            const float nfb = (dtb >= 0.0f) ? 0.0f : (-0.8f * __fdividef(dtb, dqb + 1e-6f));
            const u64 nf = pk2(nfa, nfb);
            const u64 s0 = fma2(nf, d0, p0);
            const u64 s1 = fma2(nf, d1, p1);
            const u64 s2 = fma2(nf, d2, p2);
            const u64 nn = fma2(s0, s0, fma2(s1, s1, mul2(s2, s2)));
            float na, nb; upk2(nn, na, nb);
            const u64 sn2 = pk2(sqrtf(na), sqrtf(nb));
            const u64* HR = s_wh1p[pc];
            #pragma unroll
            for (int o = 0; o < 8; o++) acc2[o] = fma2(sn2, HR[o], acc2[o]);
        }
        float h1v[8];
        #pragma unroll
        for (int o = 0; o < 8; o++) {
            float ea, eb; upk2(acc2[o], ea, eb);
            h1v[o] = fmaxf(0.0f, ea + eb);
        }

        // h2 + softmax over 8 channels (scalar)
        const float4* wh2v = (const float4*)s_wh2;
        const float4 bA = ((const float4*)s_bh2)[0];
        const float4 bB = ((const float4*)s_bh2)[1];
        float h2[8] = {bA.x, bA.y, bA.z, bA.w, bB.x, bB.y, bB.z, bB.w};
        #pragma unroll
        for (int c = 0; c < 8; c++) {
            const float4 r0 = wh2v[c*2 + 0];
            const float4 r1 = wh2v[c*2 + 1];
            const float s = h1v[c];
            h2[0] += s*r0.x; h2[1] += s*r0.y; h2[2] += s*r0.z; h2[3] += s*r0.w;
            h2[4] += s*r1.x; h2[5] += s*r1.y; h2[6] += s*r1.z; h2[7] += s*r1.w;
        }
        float m = h2[0];
        #pragma unroll
        for (int o = 1; o < 8; o++) m = fmaxf(m, h2[o]);
        float se = 0.0f;
        #pragma unroll
        for (int o = 0; o < 8; o++) { h2[o] = __expf(h2[o] - m); se += h2[o]; }
        const float ise = __fdividef(1.0f, se);
        #pragma unroll
        for (int o = 0; o < 8; o++)
            ((float*)&s_score2[warp][k][o])[pp] = h2[o] * ise;
    }
    __syncwarp();

    // ======= Phase 2: correlation, lane = channel h, packed over the 2 points =======
    u64 wbd0[8], wbd1[8], wbd2[8];
    #pragma unroll
    for (int ks = 0; ks < 8; ks++) {
        const float w0 = s_wb[      ks*32 + lane];
        const float w1 = s_wb[256 + ks*32 + lane];
        const float w2 = s_wb[512 + ks*32 + lane];
        wbd0[ks] = pk2(w0, w0); wbd1[ks] = pk2(w1, w1); wbd2[ks] = pk2(w2, w2);
    }
    {
        u64 fa0 = 0, fa1 = 0, fa2 = 0;
        #pragma unroll
        for (int kk = 0; kk < 16; kk++) {
            const u64* sc = s_score2[warp][kk];
            u64 we0 = mul2(sc[0], wbd0[0]);
            u64 we1 = mul2(sc[0], wbd1[0]);
            u64 we2 = mul2(sc[0], wbd2[0]);
            #pragma unroll
            for (int ks = 1; ks < 8; ks++) {
                we0 = fma2(sc[ks], wbd0[ks], we0);
                we1 = fma2(sc[ks], wbd1[ks], we1);
                we2 = fma2(sc[ks], wbd2[ks], we2);
            }
            const u64* L = s_local2[warp][kk];
            const u64 q0 = fma2(L[0], we0, fma2(L[3], we1, mul2(L[6], we2)));
            const u64 q1 = fma2(L[1], we0, fma2(L[4], we1, mul2(L[7], we2)));
            const u64 q2 = fma2(L[2], we0, fma2(L[5], we1, mul2(L[8], we2)));
            const u64 nn = fma2(q0, q0, fma2(q1, q1, mul2(q2, q2)));
            float n0f, n1f; upk2(nn, n0f, n1f);
            const u64 iv = pk2(rsqrtf(fmaxf(n0f, 1e-24f)), rsqrtf(fmaxf(n1f, 1e-24f)));
            fa0 = fma2(q0, iv, fa0);
            fa1 = fma2(q1, iv, fa1);
            fa2 = fma2(q2, iv, fa2);
        }
        const u64 SC = pk2(1.0f/16.0f, 1.0f/16.0f);
        s_feat2[warp][lane][0] = mul2(fa0, SC);
        s_feat2[warp][lane][1] = mul2(fa1, SC);
        s_feat2[warp][lane][2] = mul2(fa2, SC);
    }
    __syncwarp();

    // ======= Phase 3a: VNLeakyReLU(32->32), packed over points =======
    {
        u64 f0 = s_feat2[warp][lane][0];
        u64 f1 = s_feat2[warp][lane][1];
        u64 f2 = s_feat2[warp][lane][2];
        u64 g0 = 0, g1 = 0, g2 = 0;
        #pragma unroll
        for (int h = 0; h < 32; h++) {
            const float w = __ldg(wd_relu + h*32 + lane);
            const u64 w2 = pk2(w, w);
            g0 = fma2(s_feat2[warp][h][0], w2, g0);
            g1 = fma2(s_feat2[warp][h][1], w2, g1);
            g2 = fma2(s_feat2[warp][h][2], w2, g2);
        }
        const u64 dot2 = fma2(f0, g0, fma2(f1, g1, mul2(f2, g2)));
        const u64 dsq2 = fma2(g0, g0, fma2(g1, g1, mul2(g2, g2)));
        float dta, dtb, dqa, dqb;
        upk2(dot2, dta, dtb); upk2(dsq2, dqa, dqb);
        const float nfa = (dta >= 0.0f) ? 0.0f : (-0.8f * __fdividef(dta, dqa + 1e-6f));
        const float nfb = (dtb >= 0.0f) ? 0.0f : (-0.8f * __fdividef(dtb, dqb + 1e-6f));
        const u64 nf = pk2(nfa, nfb);
        __syncwarp();
        s_feat2[warp][lane][0] = fma2(nf, g0, f0);
        s_feat2[warp][lane][1] = fma2(nf, g1, f1);
        s_feat2[warp][lane][2] = fma2(nf, g2, f2);
    }
    __syncwarp();

    // ======= Phase 3b: VNLinearLeakyReLU(32->64), packed over points =======
    {
        u64 ax=0, ay=0, az=0, bx=0, by=0, bz=0;   // j = lane
        u64 Ax=0, Ay=0, Az=0, Bx=0, By=0, Bz=0;   // j = lane + 32
        #pragma unroll
        for (int h = 0; h < 32; h++) {
            const float wa0 = __ldg(w_un  + h*64 + lane);
            const float wa1 = __ldg(w_un  + h*64 + lane + 32);
            const float wd0 = __ldg(wd_un + h*64 + lane);
            const float wd1 = __ldg(wd_un + h*64 + lane + 32);
            const u64 F0 = s_feat2[warp][h][0];
            const u64 F1 = s_feat2[warp][h][1];
            const u64 F2 = s_feat2[warp][h][2];
            const u64 wa0d = pk2(wa0, wa0), wd0d = pk2(wd0, wd0);
            const u64 wa1d = pk2(wa1, wa1), wd1d = pk2(wd1, wd1);
            ax = fma2(F0, wa0d, ax); ay = fma2(F1, wa0d, ay); az = fma2(F2, wa0d, az);
            bx = fma2(F0, wd0d, bx); by = fma2(F1, wd0d, by); bz = fma2(F2, wd0d, bz);
            Ax = fma2(F0, wa1d, Ax); Ay = fma2(F1, wa1d, Ay); Az = fma2(F2, wa1d, Az);
            Bx = fma2(F0, wd1d, Bx); By = fma2(F1, wd1d, By); Bz = fma2(F2, wd1d, Bz);
        }
        float axp[2], ayp[2], azp[2], bxp[2], byp[2], bzp[2];
        float Axp[2], Ayp[2], Azp[2], Bxp[2], Byp[2], Bzp[2];
        upk2(ax, axp[0], axp[1]); upk2(ay, ayp[0], ayp[1]); upk2(az, azp[0], azp[1]);
        upk2(bx, bxp[0], bxp[1]); upk2(by, byp[0], byp[1]); upk2(bz, bzp[0], bzp[1]);
        upk2(Ax, Axp[0], Axp[1]); upk2(Ay, Ayp[0], Ayp[1]); upk2(Az, Azp[0], Azp[1]);
        upk2(Bx, Bxp[0], Bxp[1]); upk2(By, Byp[0], Byp[1]); upk2(Bz, Bzp[0], Bzp[1]);
        #pragma unroll
        for (int p = 0; p < PTS; p++) {
            if (n0 + p >= N) break;
            const int n = n0 + p;
            {
                const int j = lane;
                const float x0 = BN*axp[p], x1 = BN*ayp[p], x2 = BN*azp[p];
                const float dt = x0*bxp[p] + x1*byp[p] + x2*bzp[p];
                const float dq = bxp[p]*bxp[p] + byp[p]*byp[p] + bzp[p]*bzp[p];
                const float fc = (dt >= 0.0f) ? 0.0f : (0.8f * __fdividef(dt, dq + 1e-6f));
                out[n*192 + j*3 + 0] = x0 - fc*bxp[p];
                out[n*192 + j*3 + 1] = x1 - fc*byp[p];
                out[n*192 + j*3 + 2] = x2 - fc*bzp[p];
            }
            {
                const int j = lane + 32;
                const float x0 = BN*Axp[p], x1 = BN*Ayp[p], x2 = BN*Azp[p];
                const float dt = x0*Bxp[p] + x1*Byp[p] + x2*Bzp[p];
                const float dq = Bxp[p]*Bxp[p] + Byp[p]*Byp[p] + Bzp[p]*Bzp[p];
                const float fc = (dt >= 0.0f) ? 0.0f : (0.8f * __fdividef(dt, dq + 1e-6f));
                out[n*192 + j*3 + 0] = x0 - fc*Bxp[p];
                out[n*192 + j*3 + 1] = x1 - fc*Byp[p];
                out[n*192 + j*3 + 2] = x2 - fc*Bzp[p];
            }
        }
    }
}

extern "C" void kernel_launch(void* const* d_in, const int* in_sizes, int n_in,
                              void* d_out, int out_size) {
    const float* q_pts   = (const float*)d_in[0];
    const float* s_pts   = (const float*)d_in[1];
    const int*   nbr     = (const int*)  d_in[3];
    const float* wb      = (const float*)d_in[4];
    const float* w_vn    = (const float*)d_in[5];
    const float* wd_vn   = (const float*)d_in[6];
    const float* w_h1    = (const float*)d_in[7];
    const float* w_h2    = (const float*)d_in[8];
    const float* b_h2    = (const float*)d_in[9];
    const float* wd_relu = (const float*)d_in[10];
    const float* w_un    = (const float*)d_in[11];
    const float* wd_un   = (const float*)d_in[12];

    const int N = in_sizes[0] / 3;
    const int per_block = WARPS * PTS;
    const int blocks = (N + per_block - 1) / per_block;
    arek<<<blocks, 128>>>(q_pts, s_pts, nbr, wb, w_vn, wd_vn, w_h1, w_h2, b_h2,
                          wd_relu, w_un, wd_un, (float*)d_out, N);
}

// round 7
// speedup vs baseline: 1.1429x; 1.0008x over previous
#include <cuda_runtime.h>

typedef unsigned long long u64;
#define WARPS 4
#define PTS 2
#define FULLMASK 0xffffffffu

__device__ __forceinline__ u64 pk2(float x, float y) {
    u64 r; asm("mov.b64 %0,{%1,%2};" : "=l"(r) : "f"(x), "f"(y)); return r;
}
__device__ __forceinline__ void upk2(u64 v, float& x, float& y) {
    asm("mov.b64 {%0,%1},%2;" : "=f"(x), "=f"(y) : "l"(v));
}
__device__ __forceinline__ u64 fma2(u64 a, u64 b, u64 c) {
    u64 d; asm("fma.rn.f32x2 %0,%1,%2,%3;" : "=l"(d) : "l"(a), "l"(b), "l"(c)); return d;
}
__device__ __forceinline__ u64 mul2(u64 a, u64 b) {
    u64 d; asm("mul.rn.f32x2 %0,%1,%2;" : "=l"(d) : "l"(a), "l"(b)); return d;
}

__global__ void __launch_bounds__(128, 5) arek(
    const float* __restrict__ q_pts, const float* __restrict__ s_pts,
    const int*   __restrict__ nbr,
    const float* __restrict__ wb,     const float* __restrict__ w_vn,
    const float* __restrict__ wd_vn,  const float* __restrict__ w_h1,
    const float* __restrict__ w_h2,   const float* __restrict__ b_h2,
    const float* __restrict__ wd_relu,const float* __restrict__ w_un,
    const float* __restrict__ wd_un,
    float* __restrict__ out, int N)
{
    const float BN = 0.99999500003749968f;   // 1/sqrt(1+1e-5)

    // ---- pre-packed weights (channel pairs), 16B-aligned rows for LDS.128 ----
    __shared__ __align__(16) u64 s_wvnu2[8][6];  // [pc] -> {wx,wy | wz,ux | uy,uz} (BN in w)
    __shared__ __align__(16) u64 s_wh1p[8][8];   // [pc][o] -> (BN*w_h1[2pc][o], BN*w_h1[2pc+1][o])
    __shared__ __align__(16) float s_wh2[64];    // [8][8] row-major
    __shared__ __align__(16) float s_bh2[8];
    __shared__ float s_wb[768];
    // ---- per-warp scratch, packed over the 2 points; rows padded to 80B (LDS.128-able) ----
    __shared__ __align__(16) u64 s_local2[WARPS][16][10];  // comps 0..8 = p,c,r xyz
    __shared__ __align__(16) u64 s_score2[WARPS][16][10];  // comps 0..7 = scores
    __shared__ u64 s_feat2 [WARPS][32][3];                 // [h][comp] -> (p0,p1)

    const int tid = threadIdx.x;
    if (tid < 8) {
        const int pc = tid, c0 = 2*pc, c1 = 2*pc + 1;
        s_wvnu2[pc][0] = pk2(BN*w_vn[c0],      BN*w_vn[c1]);
        s_wvnu2[pc][1] = pk2(BN*w_vn[16+c0],   BN*w_vn[16+c1]);
        s_wvnu2[pc][2] = pk2(BN*w_vn[32+c0],   BN*w_vn[32+c1]);
        s_wvnu2[pc][3] = pk2(wd_vn[c0],        wd_vn[c1]);
        s_wvnu2[pc][4] = pk2(wd_vn[16+c0],     wd_vn[16+c1]);
        s_wvnu2[pc][5] = pk2(wd_vn[32+c0],     wd_vn[32+c1]);
    }
    if (tid < 64) {
        const int pc = tid >> 3, o = tid & 7;
        s_wh1p[pc][o] = pk2(BN*w_h1[(2*pc)*8 + o], BN*w_h1[(2*pc+1)*8 + o]);
        s_wh2[tid] = w_h2[tid];
    }
    if (tid < 8)  s_bh2[tid] = b_h2[tid];
    #pragma unroll
    for (int i = tid; i < 768; i += 128) s_wb[i] = wb[i];
    __syncthreads();

    const int warp = tid >> 5, lane = tid & 31;
    const int n0 = blockIdx.x * (WARPS * PTS) + warp * PTS;
    if (n0 >= N) return;

    // ================= Phase 1: lane = (p, k), channel-pair packed =================
    {
        const int pp = lane >> 4;            // point within pair
        const int k  = lane & 15;            // neighbor
        const int n  = (n0 + pp < N) ? (n0 + pp) : (N - 1);

        const float qx = q_pts[n*3+0], qy = q_pts[n*3+1], qz = q_pts[n*3+2];
        const int idx = nbr[n*16 + k];
        const float px = s_pts[idx*3+0] - qx;
        const float py = s_pts[idx*3+1] - qy;
        const float pz = s_pts[idx*3+2] - qz;

        float sx = px, sy = py, sz = pz;
        #pragma unroll
        for (int off = 1; off < 16; off <<= 1) {
            sx += __shfl_xor_sync(FULLMASK, sx, off);
            sy += __shfl_xor_sync(FULLMASK, sy, off);
            sz += __shfl_xor_sync(FULLMASK, sz, off);
        }
        const float cx = sx * (1.0f/16.0f);
        const float cy = sy * (1.0f/16.0f);
        const float cz = sz * (1.0f/16.0f);

        const float rx = py*cz - pz*cy;
        const float ry = pz*cx - px*cz;
        const float rz = px*cy - py*cx;

        ((float*)&s_local2[warp][k][0])[pp] = px;
        ((float*)&s_local2[warp][k][1])[pp] = py;
        ((float*)&s_local2[warp][k][2])[pp] = pz;
        ((float*)&s_local2[warp][k][3])[pp] = cx;
        ((float*)&s_local2[warp][k][4])[pp] = cy;
        ((float*)&s_local2[warp][k][5])[pp] = cz;
        ((float*)&s_local2[warp][k][6])[pp] = rx;
        ((float*)&s_local2[warp][k][7])[pp] = ry;
        ((float*)&s_local2[warp][k][8])[pp] = rz;

        const u64 PX = pk2(px,px), PY = pk2(py,py), PZ = pk2(pz,pz);
        const u64 CX = pk2(cx,cx), CY = pk2(cy,cy), CZ = pk2(cz,cz);
        const u64 RX = pk2(rx,rx), RY = pk2(ry,ry), RZ = pk2(rz,rz);

        u64 acc2[8] = {0,0,0,0,0,0,0,0};
        #pragma unroll
        for (int pc = 0; pc < 8; pc++) {
            const ulonglong2* wv = (const ulonglong2*)s_wvnu2[pc];
            const ulonglong2 wA = wv[0];   // wx, wy
            const ulonglong2 wB = wv[1];   // wz, ux
            const ulonglong2 wC = wv[2];   // uy, uz
            const u64 p0 = fma2(PX, wA.x, fma2(CX, wA.y, mul2(RX, wB.x)));
            const u64 p1 = fma2(PY, wA.x, fma2(CY, wA.y, mul2(RY, wB.x)));
            const u64 p2 = fma2(PZ, wA.x, fma2(CZ, wA.y, mul2(RZ, wB.x)));
            const u64 d0 = fma2(PX, wB.y, fma2(CX, wC.x, mul2(RX, wC.y)));
            const u64 d1 = fma2(PY, wB.y, fma2(CY, wC.x, mul2(RY, wC.y)));
            const u64 d2 = fma2(PZ, wB.y, fma2(CZ, wC.x, mul2(RZ, wC.y)));
            const u64 dot2 = fma2(p0, d0, fma2(p1, d1, mul2(p2, d2)));
            const u64 dsq2 = fma2(d0, d0, fma2(d1, d1, mul2(d2, d2)));
            float dta, dtb, dqa, dqb;
            upk2(dot2, dta, dtb); upk2(dsq2, dqa, dqb);
            const float nfa = (dta >= 0.0f) ? 0.0f : (-0.8f * __fdividef(dta, dqa + 1e-6f));
            const float nfb = (dtb >= 0.0f) ? 0.0f : (-0.8f * __fdividef(dtb, dqb + 1e-6f));
            const u64 nf = pk2(nfa, nfb);
            const u64 s0 = fma2(nf, d0, p0);
            const u64 s1 = fma2(nf, d1, p1);
            const u64 s2 = fma2(nf, d2, p2);
            const u64 nn = fma2(s0, s0, fma2(s1, s1, mul2(s2, s2)));
            float na, nb; upk2(nn, na, nb);
            const u64 sn2 = pk2(sqrtf(na), sqrtf(nb));
            const ulonglong2* hr = (const ulonglong2*)s_wh1p[pc];
            const ulonglong2 h01 = hr[0], h23 = hr[1], h45 = hr[2], h67 = hr[3];
            acc2[0] = fma2(sn2, h01.x, acc2[0]);
            acc2[1] = fma2(sn2, h01.y, acc2[1]);
            acc2[2] = fma2(sn2, h23.x, acc2[2]);
            acc2[3] = fma2(sn2, h23.y, acc2[3]);
            acc2[4] = fma2(sn2, h45.x, acc2[4]);
            acc2[5] = fma2(sn2, h45.y, acc2[5]);
            acc2[6] = fma2(sn2, h67.x, acc2[6]);
            acc2[7] = fma2(sn2, h67.y, acc2[7]);
        }
        float h1v[8];
        #pragma unroll
        for (int o = 0; o < 8; o++) {
            float ea, eb; upk2(acc2[o], ea, eb);
            h1v[o] = fmaxf(0.0f, ea + eb);
        }

        // h2 + softmax over 8 channels (scalar)
        const float4* wh2v = (const float4*)s_wh2;
        const float4 bA = ((const float4*)s_bh2)[0];
        const float4 bB = ((const float4*)s_bh2)[1];
        float h2[8] = {bA.x, bA.y, bA.z, bA.w, bB.x, bB.y, bB.z, bB.w};
        #pragma unroll
        for (int c = 0; c < 8; c++) {
            const float4 r0 = wh2v[c*2 + 0];
            const float4 r1 = wh2v[c*2 + 1];
            const float s = h1v[c];
            h2[0] += s*r0.x; h2[1] += s*r0.y; h2[2] += s*r0.z; h2[3] += s*r0.w;
            h2[4] += s*r1.x; h2[5] += s*r1.y; h2[6] += s*r1.z; h2[7] += s*r1.w;
        }
        float m = h2[0];
        #pragma unroll
        for (int o = 1; o < 8; o++) m = fmaxf(m, h2[o]);
        float se = 0.0f;
        #pragma unroll
        for (int o = 0; o < 8; o++) { h2[o] = __expf(h2[o] - m); se += h2[o]; }
        const float ise = __fdividef(1.0f, se);
        #pragma unroll
        for (int o = 0; o < 8; o++)
            ((float*)&s_score2[warp][k][o])[pp] = h2[o] * ise;
    }
    __syncwarp();

    // ======= Phase 2: correlation, lane = channel h, packed over the 2 points =======
    u64 wbd0[8], wbd1[8], wbd2[8];
    #pragma unroll
    for (int ks = 0; ks < 8; ks++) {
        const float w0 = s_wb[      ks*32 + lane];
        const float w1 = s_wb[256 + ks*32 + lane];
        const float w2 = s_wb[512 + ks*32 + lane];
        wbd0[ks] = pk2(w0, w0); wbd1[ks] = pk2(w1, w1); wbd2[ks] = pk2(w2, w2);
    }
    {
        u64 fa0 = 0, fa1 = 0, fa2 = 0;
        #pragma unroll
        for (int kk = 0; kk < 16; kk++) {
            const ulonglong2* scv = (const ulonglong2*)s_score2[warp][kk];
            const ulonglong2 sAB = scv[0], sCD = scv[1], sEF = scv[2], sGH = scv[3];
            u64 we0 = mul2(sAB.x, wbd0[0]);
            u64 we1 = mul2(sAB.x, wbd1[0]);
            u64 we2 = mul2(sAB.x, wbd2[0]);
            we0 = fma2(sAB.y, wbd0[1], we0); we1 = fma2(sAB.y, wbd1[1], we1); we2 = fma2(sAB.y, wbd2[1], we2);
            we0 = fma2(sCD.x, wbd0[2], we0); we1 = fma2(sCD.x, wbd1[2], we1); we2 = fma2(sCD.x, wbd2[2], we2);
            we0 = fma2(sCD.y, wbd0[3], we0); we1 = fma2(sCD.y, wbd1[3], we1); we2 = fma2(sCD.y, wbd2[3], we2);
            we0 = fma2(sEF.x, wbd0[4], we0); we1 = fma2(sEF.x, wbd1[4], we1); we2 = fma2(sEF.x, wbd2[4], we2);
            we0 = fma2(sEF.y, wbd0[5], we0); we1 = fma2(sEF.y, wbd1[5], we1); we2 = fma2(sEF.y, wbd2[5], we2);
            we0 = fma2(sGH.x, wbd0[6], we0); we1 = fma2(sGH.x, wbd1[6], we1); we2 = fma2(sGH.x, wbd2[6], we2);
            we0 = fma2(sGH.y, wbd0[7], we0); we1 = fma2(sGH.y, wbd1[7], we1); we2 = fma2(sGH.y, wbd2[7], we2);

            const ulonglong2* Lv = (const ulonglong2*)s_local2[warp][kk];
            const ulonglong2 L01 = Lv[0], L23 = Lv[1], L45 = Lv[2], L67 = Lv[3];
            const u64 L8 = s_local2[warp][kk][8];
            const u64 q0 = fma2(L01.x, we0, fma2(L23.y, we1, mul2(L67.x, we2)));
            const u64 q1 = fma2(L01.y, we0, fma2(L45.x, we1, mul2(L67.y, we2)));
            const u64 q2 = fma2(L23.x, we0, fma2(L45.y, we1, mul2(L8,    we2)));
            const u64 nn = fma2(q0, q0, fma2(q1, q1, mul2(q2, q2)));
            float n0f, n1f; upk2(nn, n0f, n1f);
            const u64 iv = pk2(rsqrtf(fmaxf(n0f, 1e-24f)), rsqrtf(fmaxf(n1f, 1e-24f)));
            fa0 = fma2(q0, iv, fa0);
            fa1 = fma2(q1, iv, fa1);
            fa2 = fma2(q2, iv, fa2);
        }
        const u64 SC = pk2(1.0f/16.0f, 1.0f/16.0f);
        s_feat2[warp][lane][0] = mul2(fa0, SC);
        s_feat2[warp][lane][1] = mul2(fa1, SC);
        s_feat2[warp][lane][2] = mul2(fa2, SC);
    }
    __syncwarp();

    // ======= Phase 3a: VNLeakyReLU(32->32), packed over points =======
    {
        u64 f0 = s_feat2[warp][lane][0];
        u64 f1 = s_feat2[warp][lane][1];
        u64 f2 = s_feat2[warp][lane][2];
        u64 g0 = 0, g1 = 0, g2 = 0;
        #pragma unroll
        for (int h = 0; h < 32; h++) {
            const float w = __ldg(wd_relu + h*32 + lane);
            const u64 w2 = pk2(w, w);
            g0 = fma2(s_feat2[warp][h][0], w2, g0);
            g1 = fma2(s_feat2[warp][h][1], w2, g1);
            g2 = fma2(s_feat2[warp][h][2], w2, g2);
        }
        const u64 dot2 = fma2(f0, g0, fma2(f1, g1, mul2(f2, g2)));
        const u64 dsq2 = fma2(g0, g0, fma2(g1, g1, mul2(g2, g2)));
        float dta, dtb, dqa, dqb;
        upk2(dot2, dta, dtb); upk2(dsq2, dqa, dqb);
        const float nfa = (dta >= 0.0f) ? 0.0f : (-0.8f * __fdividef(dta, dqa + 1e-6f));
        const float nfb = (dtb >= 0.0f) ? 0.0f : (-0.8f * __fdividef(dtb, dqb + 1e-6f));
        const u64 nf = pk2(nfa, nfb);
        __syncwarp();
        s_feat2[warp][lane][0] = fma2(nf, g0, f0);
        s_feat2[warp][lane][1] = fma2(nf, g1, f1);
        s_feat2[warp][lane][2] = fma2(nf, g2, f2);
    }
    __syncwarp();

    // ======= Phase 3b: VNLinearLeakyReLU(32->64), packed over points =======
    {
        u64 ax=0, ay=0, az=0, bx=0, by=0, bz=0;   // j = lane
        u64 Ax=0, Ay=0, Az=0, Bx=0, By=0, Bz=0;   // j = lane + 32
        #pragma unroll
        for (int h = 0; h < 32; h++) {
            const float wa0 = __ldg(w_un  + h*64 + lane);
            const float wa1 = __ldg(w_un  + h*64 + lane + 32);
            const float wd0 = __ldg(wd_un + h*64 + lane);
            const float wd1 = __ldg(wd_un + h*64 + lane + 32);
            const u64 F0 = s_feat2[warp][h][0];
            const u64 F1 = s_feat2[warp][h][1];
            const u64 F2 = s_feat2[warp][h][2];
            const u64 wa0d = pk2(wa0, wa0), wd0d = pk2(wd0, wd0);
            const u64 wa1d = pk2(wa1, wa1), wd1d = pk2(wd1, wd1);
            ax = fma2(F0, wa0d, ax); ay = fma2(F1, wa0d, ay); az = fma2(F2, wa0d, az);
            bx = fma2(F0, wd0d, bx); by = fma2(F1, wd0d, by); bz = fma2(F2, wd0d, bz);
            Ax = fma2(F0, wa1d, Ax); Ay = fma2(F1, wa1d, Ay); Az = fma2(F2, wa1d, Az);
            Bx = fma2(F0, wd1d, Bx); By = fma2(F1, wd1d, By); Bz = fma2(F2, wd1d, Bz);
        }
        float axp[2], ayp[2], azp[2], bxp[2], byp[2], bzp[2];
        float Axp[2], Ayp[2], Azp[2], Bxp[2], Byp[2], Bzp[2];
        upk2(ax, axp[0], axp[1]); upk2(ay, ayp[0], ayp[1]); upk2(az, azp[0], azp[1]);
        upk2(bx, bxp[0], bxp[1]); upk2(by, byp[0], byp[1]); upk2(bz, bzp[0], bzp[1]);
        upk2(Ax, Axp[0], Axp[1]); upk2(Ay, Ayp[0], Ayp[1]); upk2(Az, Azp[0], Azp[1]);
        upk2(Bx, Bxp[0], Bxp[1]); upk2(By, Byp[0], Byp[1]); upk2(Bz, Bzp[0], Bzp[1]);
        #pragma unroll
        for (int p = 0; p < PTS; p++) {
            if (n0 + p >= N) break;
            const int n = n0 + p;
            {
                const int j = lane;
                const float x0 = BN*axp[p], x1 = BN*ayp[p], x2 = BN*azp[p];
                const float dt = x0*bxp[p] + x1*byp[p] + x2*bzp[p];
                const float dq = bxp[p]*bxp[p] + byp[p]*byp[p] + bzp[p]*bzp[p];
                const float fc = (dt >= 0.0f) ? 0.0f : (0.8f * __fdividef(dt, dq + 1e-6f));
                out[n*192 + j*3 + 0] = x0 - fc*bxp[p];
                out[n*192 + j*3 + 1] = x1 - fc*byp[p];
                out[n*192 + j*3 + 2] = x2 - fc*bzp[p];
            }
            {
                const int j = lane + 32;
                const float x0 = BN*Axp[p], x1 = BN*Ayp[p], x2 = BN*Azp[p];
                const float dt = x0*Bxp[p] + x1*Byp[p] + x2*Bzp[p];
                const float dq = Bxp[p]*Bxp[p] + Byp[p]*Byp[p] + Bzp[p]*Bzp[p];
                const float fc = (dt >= 0.0f) ? 0.0f : (0.8f * __fdividef(dt, dq + 1e-6f));
                out[n*192 + j*3 + 0] = x0 - fc*Bxp[p];
                out[n*192 + j*3 + 1] = x1 - fc*Byp[p];
                out[n*192 + j*3 + 2] = x2 - fc*Bzp[p];
            }
        }
    }
}

extern "C" void kernel_launch(void* const* d_in, const int* in_sizes, int n_in,
                              void* d_out, int out_size) {
    const float* q_pts   = (const float*)d_in[0];
    const float* s_pts   = (const float*)d_in[1];
    const int*   nbr     = (const int*)  d_in[3];
    const float* wb      = (const float*)d_in[4];
    const float* w_vn    = (const float*)d_in[5];
    const float* wd_vn   = (const float*)d_in[6];
    const float* w_h1    = (const float*)d_in[7];
    const float* w_h2    = (const float*)d_in[8];
    const float* b_h2    = (const float*)d_in[9];
    const float* wd_relu = (const float*)d_in[10];
    const float* w_un    = (const float*)d_in[11];
    const float* wd_un   = (const float*)d_in[12];

    const int N = in_sizes[0] / 3;
    const int per_block = WARPS * PTS;
    const int blocks = (N + per_block - 1) / per_block;
    arek<<<blocks, 128>>>(q_pts, s_pts, nbr, wb, w_vn, wd_vn, w_h1, w_h2, b_h2,
                          wd_relu, w_un, wd_un, (float*)d_out, N);
}

// round 8
// speedup vs baseline: 1.1481x; 1.0046x over previous
#include <cuda_runtime.h>

typedef unsigned long long u64;
#define WARPS 4
#define PTS 2
#define FULLMASK 0xffffffffu

__device__ float2 g_wuni[2048];   // interleaved {w_un, wd_un}

__global__ void prep_wuni(const float* __restrict__ w_un, const float* __restrict__ wd_un) {
    const int i = blockIdx.x * blockDim.x + threadIdx.x;
    if (i < 2048) g_wuni[i] = make_float2(w_un[i], wd_un[i]);
}

__device__ __forceinline__ u64 pk2(float x, float y) {
    u64 r; asm("mov.b64 %0,{%1,%2};" : "=l"(r) : "f"(x), "f"(y)); return r;
}
__device__ __forceinline__ void upk2(u64 v, float& x, float& y) {
    asm("mov.b64 {%0,%1},%2;" : "=f"(x), "=f"(y) : "l"(v));
}
__device__ __forceinline__ u64 fma2(u64 a, u64 b, u64 c) {
    u64 d; asm("fma.rn.f32x2 %0,%1,%2,%3;" : "=l"(d) : "l"(a), "l"(b), "l"(c)); return d;
}
__device__ __forceinline__ u64 mul2(u64 a, u64 b) {
    u64 d; asm("mul.rn.f32x2 %0,%1,%2;" : "=l"(d) : "l"(a), "l"(b)); return d;
}

__global__ void __launch_bounds__(128, 6) arek(
    const float* __restrict__ q_pts, const float* __restrict__ s_pts,
    const int*   __restrict__ nbr,
    const float* __restrict__ wb,     const float* __restrict__ w_vn,
    const float* __restrict__ wd_vn,  const float* __restrict__ w_h1,
    const float* __restrict__ w_h2,   const float* __restrict__ b_h2,
    const float* __restrict__ wd_relu,
    float* __restrict__ out, int N)
{
    const float BN = 0.99999500003749968f;   // 1/sqrt(1+1e-5)

    // ---- pre-packed weights (channel pairs), 16B-aligned rows for LDS.128 ----
    __shared__ __align__(16) u64 s_wvnu2[8][6];  // [pc] -> {wx,wy | wz,ux | uy,uz} (BN in w)
    __shared__ __align__(16) u64 s_wh1p[8][8];   // [pc][o] -> (BN*w_h1[2pc][o], BN*w_h1[2pc+1][o])
    __shared__ __align__(16) u64 s_wh2p[8][4];   // [c][o2] -> (w_h2[c][2o2], w_h2[c][2o2+1])
    __shared__ __align__(16) float s_bh2[8];
    __shared__ float s_wb[768];
    // ---- per-warp scratch, packed over the 2 points; rows padded to 80B ----
    __shared__ __align__(16) u64 s_local2[WARPS][16][10];  // comps 0..8 = p,c,r xyz
    __shared__ __align__(16) u64 s_score2[WARPS][16][10];  // comps 0..7 = scores
    __shared__ u64 s_feat2 [WARPS][32][3];                 // [h][comp] -> (p0,p1)

    const int tid = threadIdx.x;
    if (tid < 8) {
        const int pc = tid, c0 = 2*pc, c1 = 2*pc + 1;
        s_wvnu2[pc][0] = pk2(BN*w_vn[c0],      BN*w_vn[c1]);
        s_wvnu2[pc][1] = pk2(BN*w_vn[16+c0],   BN*w_vn[16+c1]);
        s_wvnu2[pc][2] = pk2(BN*w_vn[32+c0],   BN*w_vn[32+c1]);
        s_wvnu2[pc][3] = pk2(wd_vn[c0],        wd_vn[c1]);
        s_wvnu2[pc][4] = pk2(wd_vn[16+c0],     wd_vn[16+c1]);
        s_wvnu2[pc][5] = pk2(wd_vn[32+c0],     wd_vn[32+c1]);
    }
    if (tid < 64) {
        const int pc = tid >> 3, o = tid & 7;
        s_wh1p[pc][o] = pk2(BN*w_h1[(2*pc)*8 + o], BN*w_h1[(2*pc+1)*8 + o]);
    }
    if (tid >= 64 && tid < 96) {
        const int c = (tid - 64) >> 2, o2 = tid & 3;
        s_wh2p[c][o2] = pk2(w_h2[c*8 + 2*o2], w_h2[c*8 + 2*o2 + 1]);
    }
    if (tid < 8)  s_bh2[tid] = b_h2[tid];
    #pragma unroll
    for (int i = tid; i < 768; i += 128) s_wb[i] = wb[i];
    __syncthreads();

    const int warp = tid >> 5, lane = tid & 31;
    const int n0 = blockIdx.x * (WARPS * PTS) + warp * PTS;
    if (n0 >= N) return;

    // ================= Phase 1: lane = (p, k), channel-pair packed =================
    {
        const int pp = lane >> 4;            // point within pair
        const int k  = lane & 15;            // neighbor
        const int n  = (n0 + pp < N) ? (n0 + pp) : (N - 1);

        const float qx = q_pts[n*3+0], qy = q_pts[n*3+1], qz = q_pts[n*3+2];
        const int idx = nbr[n*16 + k];
        const float px = s_pts[idx*3+0] - qx;
        const float py = s_pts[idx*3+1] - qy;
        const float pz = s_pts[idx*3+2] - qz;

        float sx = px, sy = py, sz = pz;
        #pragma unroll
        for (int off = 1; off < 16; off <<= 1) {
            sx += __shfl_xor_sync(FULLMASK, sx, off);
            sy += __shfl_xor_sync(FULLMASK, sy, off);
            sz += __shfl_xor_sync(FULLMASK, sz, off);
        }
        const float cx = sx * (1.0f/16.0f);
        const float cy = sy * (1.0f/16.0f);
        const float cz = sz * (1.0f/16.0f);

        const float rx = py*cz - pz*cy;
        const float ry = pz*cx - px*cz;
        const float rz = px*cy - py*cx;

        ((float*)&s_local2[warp][k][0])[pp] = px;
        ((float*)&s_local2[warp][k][1])[pp] = py;
        ((float*)&s_local2[warp][k][2])[pp] = pz;
        ((float*)&s_local2[warp][k][3])[pp] = cx;
        ((float*)&s_local2[warp][k][4])[pp] = cy;
        ((float*)&s_local2[warp][k][5])[pp] = cz;
        ((float*)&s_local2[warp][k][6])[pp] = rx;
        ((float*)&s_local2[warp][k][7])[pp] = ry;
        ((float*)&s_local2[warp][k][8])[pp] = rz;

        const u64 PX = pk2(px,px), PY = pk2(py,py), PZ = pk2(pz,pz);
        const u64 CX = pk2(cx,cx), CY = pk2(cy,cy), CZ = pk2(cz,cz);
        const u64 RX = pk2(rx,rx), RY = pk2(ry,ry), RZ = pk2(rz,rz);

        u64 acc2[8] = {0,0,0,0,0,0,0,0};
        #pragma unroll
        for (int pc = 0; pc < 8; pc++) {
            const ulonglong2* wv = (const ulonglong2*)s_wvnu2[pc];
            const ulonglong2 wA = wv[0];   // wx, wy
            const ulonglong2 wB = wv[1];   // wz, ux
            const ulonglong2 wC = wv[2];   // uy, uz
            const u64 p0 = fma2(PX, wA.x, fma2(CX, wA.y, mul2(RX, wB.x)));
            const u64 p1 = fma2(PY, wA.x, fma2(CY, wA.y, mul2(RY, wB.x)));
            const u64 p2 = fma2(PZ, wA.x, fma2(CZ, wA.y, mul2(RZ, wB.x)));
            const u64 d0 = fma2(PX, wB.y, fma2(CX, wC.x, mul2(RX, wC.y)));
            const u64 d1 = fma2(PY, wB.y, fma2(CY, wC.x, mul2(RY, wC.y)));
            const u64 d2 = fma2(PZ, wB.y, fma2(CZ, wC.x, mul2(RZ, wC.y)));
            const u64 dot2 = fma2(p0, d0, fma2(p1, d1, mul2(p2, d2)));
            const u64 dsq2 = fma2(d0, d0, fma2(d1, d1, mul2(d2, d2)));
            float dta, dtb, dqa, dqb;
            upk2(dot2, dta, dtb); upk2(dsq2, dqa, dqb);
            const float nfa = (dta >= 0.0f) ? 0.0f : (-0.8f * __fdividef(dta, dqa + 1e-6f));
            const float nfb = (dtb >= 0.0f) ? 0.0f : (-0.8f * __fdividef(dtb, dqb + 1e-6f));
            const u64 nf = pk2(nfa, nfb);
            const u64 s0 = fma2(nf, d0, p0);
            const u64 s1 = fma2(nf, d1, p1);
            const u64 s2 = fma2(nf, d2, p2);
            const u64 nn = fma2(s0, s0, fma2(s1, s1, mul2(s2, s2)));
            float na, nb; upk2(nn, na, nb);
            const u64 sn2 = pk2(sqrtf(na), sqrtf(nb));
            const ulonglong2* hr = (const ulonglong2*)s_wh1p[pc];
            const ulonglong2 h01 = hr[0], h23 = hr[1], h45 = hr[2], h67 = hr[3];
            acc2[0] = fma2(sn2, h01.x, acc2[0]);
            acc2[1] = fma2(sn2, h01.y, acc2[1]);
            acc2[2] = fma2(sn2, h23.x, acc2[2]);
            acc2[3] = fma2(sn2, h23.y, acc2[3]);
            acc2[4] = fma2(sn2, h45.x, acc2[4]);
            acc2[5] = fma2(sn2, h45.y, acc2[5]);
            acc2[6] = fma2(sn2, h67.x, acc2[6]);
            acc2[7] = fma2(sn2, h67.y, acc2[7]);
        }
        float h1v[8];
        #pragma unroll
        for (int o = 0; o < 8; o++) {
            float ea, eb; upk2(acc2[o], ea, eb);
            h1v[o] = fmaxf(0.0f, ea + eb);
        }

        // h2 (f32x2-packed) + softmax over 8 channels
        const float4 bA = ((const float4*)s_bh2)[0];
        const float4 bB = ((const float4*)s_bh2)[1];
        u64 h2p[4] = { pk2(bA.x, bA.y), pk2(bA.z, bA.w), pk2(bB.x, bB.y), pk2(bB.z, bB.w) };
        #pragma unroll
        for (int c = 0; c < 8; c++) {
            const ulonglong2* wr = (const ulonglong2*)s_wh2p[c];
            const ulonglong2 wr01 = wr[0], wr23 = wr[1];
            const u64 sd = pk2(h1v[c], h1v[c]);
            h2p[0] = fma2(sd, wr01.x, h2p[0]);
            h2p[1] = fma2(sd, wr01.y, h2p[1]);
            h2p[2] = fma2(sd, wr23.x, h2p[2]);
            h2p[3] = fma2(sd, wr23.y, h2p[3]);
        }
        float h2[8];
        upk2(h2p[0], h2[0], h2[1]); upk2(h2p[1], h2[2], h2[3]);
        upk2(h2p[2], h2[4], h2[5]); upk2(h2p[3], h2[6], h2[7]);
        float m = h2[0];
        #pragma unroll
        for (int o = 1; o < 8; o++) m = fmaxf(m, h2[o]);
        float se = 0.0f;
        #pragma unroll
        for (int o = 0; o < 8; o++) { h2[o] = __expf(h2[o] - m); se += h2[o]; }
        const float ise = __fdividef(1.0f, se);
        #pragma unroll
        for (int o = 0; o < 8; o++)
            ((float*)&s_score2[warp][k][o])[pp] = h2[o] * ise;
    }
    __syncwarp();

    // ======= Phase 2: correlation, lane = channel h, packed over the 2 points =======
    u64 wbd0[8], wbd1[8], wbd2[8];
    #pragma unroll
    for (int ks = 0; ks < 8; ks++) {
        const float w0 = s_wb[      ks*32 + lane];
        const float w1 = s_wb[256 + ks*32 + lane];
        const float w2 = s_wb[512 + ks*32 + lane];
        wbd0[ks] = pk2(w0, w0); wbd1[ks] = pk2(w1, w1); wbd2[ks] = pk2(w2, w2);
    }
    {
        u64 fa0 = 0, fa1 = 0, fa2 = 0;
        #pragma unroll
        for (int kk = 0; kk < 16; kk++) {
            const ulonglong2* scv = (const ulonglong2*)s_score2[warp][kk];
            const ulonglong2 sAB = scv[0], sCD = scv[1], sEF = scv[2], sGH = scv[3];
            u64 we0 = mul2(sAB.x, wbd0[0]);
            u64 we1 = mul2(sAB.x, wbd1[0]);
            u64 we2 = mul2(sAB.x, wbd2[0]);
            we0 = fma2(sAB.y, wbd0[1], we0); we1 = fma2(sAB.y, wbd1[1], we1); we2 = fma2(sAB.y, wbd2[1], we2);
            we0 = fma2(sCD.x, wbd0[2], we0); we1 = fma2(sCD.x, wbd1[2], we1); we2 = fma2(sCD.x, wbd2[2], we2);
            we0 = fma2(sCD.y, wbd0[3], we0); we1 = fma2(sCD.y, wbd1[3], we1); we2 = fma2(sCD.y, wbd2[3], we2);
            we0 = fma2(sEF.x, wbd0[4], we0); we1 = fma2(sEF.x, wbd1[4], we1); we2 = fma2(sEF.x, wbd2[4], we2);
            we0 = fma2(sEF.y, wbd0[5], we0); we1 = fma2(sEF.y, wbd1[5], we1); we2 = fma2(sEF.y, wbd2[5], we2);
            we0 = fma2(sGH.x, wbd0[6], we0); we1 = fma2(sGH.x, wbd1[6], we1); we2 = fma2(sGH.x, wbd2[6], we2);
            we0 = fma2(sGH.y, wbd0[7], we0); we1 = fma2(sGH.y, wbd1[7], we1); we2 = fma2(sGH.y, wbd2[7], we2);

            const ulonglong2* Lv = (const ulonglong2*)s_local2[warp][kk];
            const ulonglong2 L01 = Lv[0], L23 = Lv[1], L45 = Lv[2], L67 = Lv[3];
            const u64 L8 = s_local2[warp][kk][8];
            const u64 q0 = fma2(L01.x, we0, fma2(L23.y, we1, mul2(L67.x, we2)));
            const u64 q1 = fma2(L01.y, we0, fma2(L45.x, we1, mul2(L67.y, we2)));
            const u64 q2 = fma2(L23.x, we0, fma2(L45.y, we1, mul2(L8,    we2)));
            const u64 nn = fma2(q0, q0, fma2(q1, q1, mul2(q2, q2)));
            float n0f, n1f; upk2(nn, n0f, n1f);
            const u64 iv = pk2(rsqrtf(fmaxf(n0f, 1e-24f)), rsqrtf(fmaxf(n1f, 1e-24f)));
            fa0 = fma2(q0, iv, fa0);
            fa1 = fma2(q1, iv, fa1);
            fa2 = fma2(q2, iv, fa2);
        }
        const u64 SC = pk2(1.0f/16.0f, 1.0f/16.0f);
        s_feat2[warp][lane][0] = mul2(fa0, SC);
        s_feat2[warp][lane][1] = mul2(fa1, SC);
        s_feat2[warp][lane][2] = mul2(fa2, SC);
    }
    __syncwarp();

    // ======= Phase 3a: VNLeakyReLU(32->32), packed over points =======
    {
        u64 f0 = s_feat2[warp][lane][0];
        u64 f1 = s_feat2[warp][lane][1];
        u64 f2 = s_feat2[warp][lane][2];
        u64 g0 = 0, g1 = 0, g2 = 0;
        #pragma unroll
        for (int h = 0; h < 32; h++) {
            const float w = __ldg(wd_relu + h*32 + lane);
            const u64 w2 = pk2(w, w);
            g0 = fma2(s_feat2[warp][h][0], w2, g0);
            g1 = fma2(s_feat2[warp][h][1], w2, g1);
            g2 = fma2(s_feat2[warp][h][2], w2, g2);
        }
        const u64 dot2 = fma2(f0, g0, fma2(f1, g1, mul2(f2, g2)));
        const u64 dsq2 = fma2(g0, g0, fma2(g1, g1, mul2(g2, g2)));
        float dta, dtb, dqa, dqb;
        upk2(dot2, dta, dtb); upk2(dsq2, dqa, dqb);
        const float nfa = (dta >= 0.0f) ? 0.0f : (-0.8f * __fdividef(dta, dqa + 1e-6f));
        const float nfb = (dtb >= 0.0f) ? 0.0f : (-0.8f * __fdividef(dtb, dqb + 1e-6f));
        const u64 nf = pk2(nfa, nfb);
        __syncwarp();
        s_feat2[warp][lane][0] = fma2(nf, g0, f0);
        s_feat2[warp][lane][1] = fma2(nf, g1, f1);
        s_feat2[warp][lane][2] = fma2(nf, g2, f2);
    }
    __syncwarp();

    // ======= Phase 3b: VNLinearLeakyReLU(32->64), interleaved weights, packed =======
    {
        u64 ax=0, ay=0, az=0, bx=0, by=0, bz=0;   // j = lane
        u64 Ax=0, Ay=0, Az=0, Bx=0, By=0, Bz=0;   // j = lane + 32
        #pragma unroll
        for (int h = 0; h < 32; h++) {
            const float2 wv0 = g_wuni[h*64 + lane];        // {w_un, wd_un} at j=lane
            const float2 wv1 = g_wuni[h*64 + lane + 32];   // {w_un, wd_un} at j=lane+32
            const u64 F0 = s_feat2[warp][h][0];
            const u64 F1 = s_feat2[warp][h][1];
            const u64 F2 = s_feat2[warp][h][2];
            const u64 wa0d = pk2(wv0.x, wv0.x), wd0d = pk2(wv0.y, wv0.y);
            const u64 wa1d = pk2(wv1.x, wv1.x), wd1d = pk2(wv1.y, wv1.y);
            ax = fma2(F0, wa0d, ax); ay = fma2(F1, wa0d, ay); az = fma2(F2, wa0d, az);
            bx = fma2(F0, wd0d, bx); by = fma2(F1, wd0d, by); bz = fma2(F2, wd0d, bz);
            Ax = fma2(F0, wa1d, Ax); Ay = fma2(F1, wa1d, Ay); Az = fma2(F2, wa1d, Az);
            Bx = fma2(F0, wd1d, Bx); By = fma2(F1, wd1d, By); Bz = fma2(F2, wd1d, Bz);
        }
        float axp[2], ayp[2], azp[2], bxp[2], byp[2], bzp[2];
        float Axp[2], Ayp[2], Azp[2], Bxp[2], Byp[2], Bzp[2];
        upk2(ax, axp[0], axp[1]); upk2(ay, ayp[0], ayp[1]); upk2(az, azp[0], azp[1]);
        upk2(bx, bxp[0], bxp[1]); upk2(by, byp[0], byp[1]); upk2(bz, bzp[0], bzp[1]);
        upk2(Ax, Axp[0], Axp[1]); upk2(Ay, Ayp[0], Ayp[1]); upk2(Az, Azp[0], Azp[1]);
        upk2(Bx, Bxp[0], Bxp[1]); upk2(By, Byp[0], Byp[1]); upk2(Bz, Bzp[0], Bzp[1]);
        #pragma unroll
        for (int p = 0; p < PTS; p++) {
            if (n0 + p >= N) break;
            const int n = n0 + p;
            {
                const int j = lane;
                const float x0 = BN*axp[p], x1 = BN*ayp[p], x2 = BN*azp[p];
                const float dt = x0*bxp[p] + x1*byp[p] + x2*bzp[p];
                const float dq = bxp[p]*bxp[p] + byp[p]*byp[p] + bzp[p]*bzp[p];
                const float fc = (dt >= 0.0f) ? 0.0f : (0.8f * __fdividef(dt, dq + 1e-6f));
                out[n*192 + j*3 + 0] = x0 - fc*bxp[p];
                out[n*192 + j*3 + 1] = x1 - fc*byp[p];
                out[n*192 + j*3 + 2] = x2 - fc*bzp[p];
            }
            {
                const int j = lane + 32;
                const float x0 = BN*Axp[p], x1 = BN*Ayp[p], x2 = BN*Azp[p];
                const float dt = x0*Bxp[p] + x1*Byp[p] + x2*Bzp[p];
                const float dq = Bxp[p]*Bxp[p] + Byp[p]*Byp[p] + Bzp[p]*Bzp[p];
                const float fc = (dt >= 0.0f) ? 0.0f : (0.8f * __fdividef(dt, dq + 1e-6f));
                out[n*192 + j*3 + 0] = x0 - fc*Bxp[p];
                out[n*192 + j*3 + 1] = x1 - fc*Byp[p];
                out[n*192 + j*3 + 2] = x2 - fc*Bzp[p];
            }
        }
    }
}

extern "C" void kernel_launch(void* const* d_in, const int* in_sizes, int n_in,
                              void* d_out, int out_size) {
    const float* q_pts   = (const float*)d_in[0];
    const float* s_pts   = (const float*)d_in[1];
    const int*   nbr     = (const int*)  d_in[3];
    const float* wb      = (const float*)d_in[4];
    const float* w_vn    = (const float*)d_in[5];
    const float* wd_vn   = (const float*)d_in[6];
    const float* w_h1    = (const float*)d_in[7];
    const float* w_h2    = (const float*)d_in[8];
    const float* b_h2    = (const float*)d_in[9];
    const float* wd_relu = (const float*)d_in[10];
    const float* w_un    = (const float*)d_in[11];
    const float* wd_un   = (const float*)d_in[12];

    const int N = in_sizes[0] / 3;
    prep_wuni<<<8, 256>>>(w_un, wd_un);
    const int per_block = WARPS * PTS;
    const int blocks = (N + per_block - 1) / per_block;
    arek<<<blocks, 128>>>(q_pts, s_pts, nbr, wb, w_vn, wd_vn, w_h1, w_h2, b_h2,
                          wd_relu, (float*)d_out, N);
}